// round 1
// baseline (speedup 1.0000x reference)
#include <cuda_runtime.h>
#include <mma.h>
#include <cmath>

using namespace nvcuda;

// ---------------- problem constants ----------------
#define NWIN   8192          // 8 * 32 * 32 windows
#define TTOK   401408        // NWIN * 49 tokens
#define HWI    224
#define HWSQ   50176         // 224*224
#define DIMC   192

// scratch (allocation-free: static device arrays)
__device__ float g_h1 [(size_t)TTOK * DIMC];   // x + attn branch (pre-LN2)
__device__ float g_h1n[(size_t)TTOK * DIMC];   // LN2(h1)

typedef wmma::fragment<wmma::matrix_a,16,16,8,wmma::precision::tf32,wmma::row_major> FragA;
typedef wmma::fragment<wmma::matrix_b,16,16,8,wmma::precision::tf32,wmma::row_major> FragB;
typedef wmma::fragment<wmma::matrix_b,16,16,8,wmma::precision::tf32,wmma::col_major> FragBT;
typedef wmma::fragment<wmma::accumulator,16,16,8,float> FragC;

template <class F>
__device__ __forceinline__ void to_tf32(F& f) {
#pragma unroll
    for (int i = 0; i < f.num_elements; i++) f.x[i] = wmma::__float_to_tf32(f.x[i]);
}

// ============================================================================
// Kernel 1: per-window fused  gather -> LN1 -> QKV -> attention -> proj ->
//           +residual -> LN2 ; writes h1 and h1n in window-token order [T,192]
// smem layout (floats):
//   xs  [64][200]  : xn (A of QKV) -> attn-out (A of proj) -> h1 row buffer
//   qk  [64][576]  : qkv           -> proj output (ld 200)
//   sb  [64][72]   : per-head scores / probs
// ============================================================================
#define XS_LD 200
#define QK_LD 576
#define SB_LD 72
#define SM_XS 0
#define SM_QK 12800
#define SM_SB 49664
#define SM_ATTN_FLOATS 54272   // 217,088 bytes

__global__ void __launch_bounds__(256, 1)
attn_kernel(const float* __restrict__ x,
            const float* __restrict__ ln1w, const float* __restrict__ ln1b,
            const float* __restrict__ qkvw, const float* __restrict__ qkvb,
            const float* __restrict__ projw, const float* __restrict__ projb,
            const float* __restrict__ rpb,
            const float* __restrict__ ln2w, const float* __restrict__ ln2b,
            const int*   __restrict__ relidx)
{
    extern __shared__ float sm[];
    float* xs = sm + SM_XS;
    float* qk = sm + SM_QK;
    float* sb = sm + SM_SB;

    const int tid  = threadIdx.x;
    const int wid  = tid >> 5;
    const int lane = tid & 31;

    const int win = blockIdx.x;
    const int b   = win >> 10;
    const int wh  = (win >> 5) & 31;
    const int ww  = win & 31;
    const float* xb = x + (size_t)b * DIMC * HWSQ;

    // ---- zero pad rows 49..63 of xs (wmma A padding) ----
    for (int i = 49 * XS_LD + tid; i < 64 * XS_LD; i += 256) xs[i] = 0.f;
    // ---- gather window: xs[r][c] = x[b,c, wh*7+r/7, ww*7+r%7] ----
    for (int idx = tid; idx < DIMC * 49; idx += 256) {
        int c = idx / 49, r = idx - c * 49;
        int i = r / 7, j = r - i * 7;
        xs[r * XS_LD + c] = xb[(size_t)c * HWSQ + (wh * 7 + i) * HWI + (ww * 7 + j)];
    }
    __syncthreads();

    // ---- LN1 in-place (warp per row) ----
    for (int r = wid; r < 49; r += 8) {
        float v[6]; float s = 0.f;
#pragma unroll
        for (int q = 0; q < 6; q++) { v[q] = xs[r * XS_LD + lane + q * 32]; s += v[q]; }
#pragma unroll
        for (int o = 16; o; o >>= 1) s += __shfl_xor_sync(~0u, s, o);
        float mu = s * (1.f / 192.f);
        float vs = 0.f;
#pragma unroll
        for (int q = 0; q < 6; q++) { float d = v[q] - mu; vs += d * d; }
#pragma unroll
        for (int o = 16; o; o >>= 1) vs += __shfl_xor_sync(~0u, vs, o);
        float rs = rsqrtf(vs * (1.f / 192.f) + 1e-5f);
#pragma unroll
        for (int q = 0; q < 6; q++) {
            int c = lane + q * 32;
            xs[r * XS_LD + c] = (v[q] - mu) * rs * ln1w[c] + ln1b[c];
        }
    }
    __syncthreads();

    // ---- QKV GEMM: [64,192] x [192,576] -> qk ----
    for (int ct = wid; ct < 36; ct += 8) {
        FragC acc[4];
#pragma unroll
        for (int rt = 0; rt < 4; rt++) wmma::fill_fragment(acc[rt], 0.f);
        for (int k = 0; k < 24; k++) {
            FragB bf;
            wmma::load_matrix_sync(bf, qkvw + (size_t)k * 8 * 576 + ct * 16, 576);
            to_tf32(bf);
#pragma unroll
            for (int rt = 0; rt < 4; rt++) {
                FragA af;
                wmma::load_matrix_sync(af, xs + rt * 16 * XS_LD + k * 8, XS_LD);
                to_tf32(af);
                wmma::mma_sync(acc[rt], af, bf, acc[rt]);
            }
        }
#pragma unroll
        for (int rt = 0; rt < 4; rt++)
            wmma::store_matrix_sync(qk + rt * 16 * QK_LD + ct * 16, acc[rt], QK_LD, wmma::mem_row_major);
    }
    __syncthreads();
    // qkv bias (real rows only; pad rows stay 0)
    for (int idx = tid; idx < 49 * 576; idx += 256) {
        int r = idx / 576, c = idx - r * 576;
        qk[r * QK_LD + c] += qkvb[c];
    }
    __syncthreads();

    // ---- attention per head ----
    const float scale = 0.17677669529663687f; // 1/sqrt(32)
    for (int h = 0; h < 6; h++) {
        // scores = Q @ K^T  (64x64x32), pad cols/rows are exactly 0
        {
            int tile = wid; // 16 tiles / 8 warps = 2 each
            for (; tile < 16; tile += 8) {
                int rt = tile >> 2, ctt = tile & 3;
                FragC acc; wmma::fill_fragment(acc, 0.f);
#pragma unroll
                for (int k = 0; k < 4; k++) {
                    FragA af;
                    wmma::load_matrix_sync(af, qk + rt * 16 * QK_LD + h * 32 + k * 8, QK_LD);
                    to_tf32(af);
                    FragBT bf;
                    wmma::load_matrix_sync(bf, qk + ctt * 16 * QK_LD + 192 + h * 32 + k * 8, QK_LD);
                    to_tf32(bf);
                    wmma::mma_sync(acc, af, bf, acc);
                }
                wmma::store_matrix_sync(sb + rt * 16 * SB_LD + ctt * 16, acc, SB_LD, wmma::mem_row_major);
            }
        }
        __syncthreads();
        // softmax over j<49 with scale + relative position bias
        for (int r = wid; r < 49; r += 8) {
            int j0 = lane, j1 = lane + 32;
            float v0 = sb[r * SB_LD + j0] * scale + rpb[relidx[r * 49 + j0] * 6 + h];
            float v1 = -1e30f;
            if (j1 < 49) v1 = sb[r * SB_LD + j1] * scale + rpb[relidx[r * 49 + j1] * 6 + h];
            float m = fmaxf(v0, v1);
#pragma unroll
            for (int o = 16; o; o >>= 1) m = fmaxf(m, __shfl_xor_sync(~0u, m, o));
            float e0 = expf(v0 - m);
            float e1 = (j1 < 49) ? expf(v1 - m) : 0.f;
            float s = e0 + e1;
#pragma unroll
            for (int o = 16; o; o >>= 1) s += __shfl_xor_sync(~0u, s, o);
            float inv = 1.f / s;
            sb[r * SB_LD + j0] = e0 * inv;
            if (j1 < 49) sb[r * SB_LD + j1] = e1 * inv;
        }
        __syncthreads();
        // out = P @ V  -> xs cols [h*32, h*32+32)
        {
            int tile = wid; // 8 tiles, one per warp
            if (tile < 8) {
                int rt = tile >> 1, ctt = tile & 1;
                FragC acc; wmma::fill_fragment(acc, 0.f);
#pragma unroll
                for (int k = 0; k < 8; k++) {
                    FragA af;
                    wmma::load_matrix_sync(af, sb + rt * 16 * SB_LD + k * 8, SB_LD);
                    to_tf32(af);
                    FragB bf;
                    wmma::load_matrix_sync(bf, qk + k * 8 * QK_LD + 384 + h * 32 + ctt * 16, QK_LD);
                    to_tf32(bf);
                    wmma::mma_sync(acc, af, bf, acc);
                }
                wmma::store_matrix_sync(xs + rt * 16 * XS_LD + h * 32 + ctt * 16, acc, XS_LD, wmma::mem_row_major);
            }
        }
        __syncthreads();
    }

    // ---- proj GEMM: xs[64,192] x projw[192,192] -> qk region (ld 200) ----
    for (int ct = wid; ct < 12; ct += 8) {
        FragC acc[4];
#pragma unroll
        for (int rt = 0; rt < 4; rt++) wmma::fill_fragment(acc[rt], 0.f);
        for (int k = 0; k < 24; k++) {
            FragB bf;
            wmma::load_matrix_sync(bf, projw + (size_t)k * 8 * 192 + ct * 16, 192);
            to_tf32(bf);
#pragma unroll
            for (int rt = 0; rt < 4; rt++) {
                FragA af;
                wmma::load_matrix_sync(af, xs + rt * 16 * XS_LD + k * 8, XS_LD);
                to_tf32(af);
                wmma::mma_sync(acc[rt], af, bf, acc[rt]);
            }
        }
#pragma unroll
        for (int rt = 0; rt < 4; rt++)
            wmma::store_matrix_sync(qk + rt * 16 * XS_LD + ct * 16, acc[rt], XS_LD, wmma::mem_row_major);
    }
    __syncthreads();

    // ---- residual: h1 = x + proj + proj_b  (re-gather x), into xs ----
    for (int idx = tid; idx < DIMC * 49; idx += 256) {
        int c = idx / 49, r = idx - c * 49;
        int i = r / 7, j = r - i * 7;
        float xv = xb[(size_t)c * HWSQ + (wh * 7 + i) * HWI + (ww * 7 + j)];
        xs[r * XS_LD + c] = xv + qk[r * XS_LD + c] + projb[c];
    }
    __syncthreads();

    // ---- LN2 + write h1 / h1n (coalesced, window-token order) ----
    size_t base = (size_t)win * 49 * DIMC;
    for (int r = wid; r < 49; r += 8) {
        float v[6]; float s = 0.f;
#pragma unroll
        for (int q = 0; q < 6; q++) { v[q] = xs[r * XS_LD + lane + q * 32]; s += v[q]; }
#pragma unroll
        for (int o = 16; o; o >>= 1) s += __shfl_xor_sync(~0u, s, o);
        float mu = s * (1.f / 192.f);
        float vs = 0.f;
#pragma unroll
        for (int q = 0; q < 6; q++) { float d = v[q] - mu; vs += d * d; }
#pragma unroll
        for (int o = 16; o; o >>= 1) vs += __shfl_xor_sync(~0u, vs, o);
        float rs = rsqrtf(vs * (1.f / 192.f) + 1e-5f);
#pragma unroll
        for (int q = 0; q < 6; q++) {
            int c = lane + q * 32;
            float hv = v[q];
            g_h1 [base + r * DIMC + c] = hv;
            g_h1n[base + r * DIMC + c] = (hv - mu) * rs * ln2w[c] + ln2b[c];
        }
    }
}

// ============================================================================
// Kernel 2: fused MLP per 64-token tile:
//   out = h1 + gelu(h1n @ fc1_w + b1) @ fc2_w + b2  (split-K over 2x384)
//   then scatter to NCHW output.
// smem: as[64][200], mb[64][392], ob[64][200]
// ============================================================================
#define AS_LD 200
#define MB_LD 392
#define OB_LD 200
#define SM_AS 0
#define SM_MB 12800
#define SM_OB 37888
#define SM_MLP_FLOATS 50688   // 202,752 bytes

__global__ void __launch_bounds__(256, 1)
mlp_kernel(const float* __restrict__ fc1w, const float* __restrict__ fc1b,
           const float* __restrict__ fc2w, const float* __restrict__ fc2b,
           float* __restrict__ out)
{
    extern __shared__ float sm[];
    float* as = sm + SM_AS;
    float* mb = sm + SM_MB;
    float* ob = sm + SM_OB;

    const int tid = threadIdx.x;
    const int wid = tid >> 5;
    const int t0  = blockIdx.x * 64;

    // load h1n tile (coalesced) + zero output accumulator
    for (int idx = tid; idx < 64 * DIMC; idx += 256) {
        int r = idx / DIMC, c = idx - r * DIMC;
        as[r * AS_LD + c] = g_h1n[(size_t)(t0 + r) * DIMC + c];
    }
    for (int idx = tid; idx < 64 * OB_LD; idx += 256) ob[idx] = 0.f;
    __syncthreads();

    for (int half = 0; half < 2; half++) {
        // GEMM1: [64,192] x [192,384] -> mb
        for (int ct = wid; ct < 24; ct += 8) {
            FragC acc[4];
#pragma unroll
            for (int rt = 0; rt < 4; rt++) wmma::fill_fragment(acc[rt], 0.f);
            for (int k = 0; k < 24; k++) {
                FragB bf;
                wmma::load_matrix_sync(bf, fc1w + (size_t)k * 8 * 768 + half * 384 + ct * 16, 768);
                to_tf32(bf);
#pragma unroll
                for (int rt = 0; rt < 4; rt++) {
                    FragA af;
                    wmma::load_matrix_sync(af, as + rt * 16 * AS_LD + k * 8, AS_LD);
                    to_tf32(af);
                    wmma::mma_sync(acc[rt], af, bf, acc[rt]);
                }
            }
#pragma unroll
            for (int rt = 0; rt < 4; rt++)
                wmma::store_matrix_sync(mb + rt * 16 * MB_LD + ct * 16, acc[rt], MB_LD, wmma::mem_row_major);
        }
        __syncthreads();
        // bias + exact GELU
        for (int idx = tid; idx < 64 * 384; idx += 256) {
            int r = idx / 384, c = idx - r * 384;
            float v = mb[r * MB_LD + c] + fc1b[half * 384 + c];
            mb[r * MB_LD + c] = 0.5f * v * (1.f + erff(v * 0.70710678118654752f));
        }
        __syncthreads();
        // GEMM2 (accumulate into ob): [64,384] x [384,192]
        for (int ct = wid; ct < 12; ct += 8) {
            FragC acc[4];
#pragma unroll
            for (int rt = 0; rt < 4; rt++)
                wmma::load_matrix_sync(acc[rt], ob + rt * 16 * OB_LD + ct * 16, OB_LD, wmma::mem_row_major);
            for (int k = 0; k < 48; k++) {
                FragB bf;
                wmma::load_matrix_sync(bf, fc2w + (size_t)(half * 384 + k * 8) * 192 + ct * 16, 192);
                to_tf32(bf);
#pragma unroll
                for (int rt = 0; rt < 4; rt++) {
                    FragA af;
                    wmma::load_matrix_sync(af, mb + rt * 16 * MB_LD + k * 8, MB_LD);
                    to_tf32(af);
                    wmma::mma_sync(acc[rt], af, bf, acc[rt]);
                }
            }
#pragma unroll
            for (int rt = 0; rt < 4; rt++)
                wmma::store_matrix_sync(ob + rt * 16 * OB_LD + ct * 16, acc[rt], OB_LD, wmma::mem_row_major);
        }
        __syncthreads();
    }

    // load h1 tile into as (coalesced)
    for (int idx = tid; idx < 64 * DIMC; idx += 256) {
        int r = idx / DIMC, c = idx - r * DIMC;
        as[r * AS_LD + c] = g_h1[(size_t)(t0 + r) * DIMC + c];
    }
    __syncthreads();

    // final residual + bias + scatter to NCHW
    for (int idx = tid; idx < 64 * DIMC; idx += 256) {
        int r = idx & 63;          // consecutive threads -> consecutive tokens
        int c = idx >> 6;
        int t = t0 + r;
        int win = t / 49; int pos = t - win * 49;
        int b  = win >> 10;
        int wh = (win >> 5) & 31;
        int ww = win & 31;
        int pi = pos / 7;
        int hh = wh * 7 + pi;
        int wx = ww * 7 + (pos - pi * 7);
        out[((size_t)(b * DIMC + c)) * HWSQ + hh * HWI + wx] =
            as[r * AS_LD + c] + ob[r * OB_LD + c] + fc2b[c];
    }
}

// ============================================================================
extern "C" void kernel_launch(void* const* d_in, const int* in_sizes, int n_in,
                              void* d_out, int out_size)
{
    (void)in_sizes; (void)n_in; (void)out_size;
    const float* x     = (const float*)d_in[0];
    const float* ln1w  = (const float*)d_in[1];
    const float* ln1b  = (const float*)d_in[2];
    const float* qkvw  = (const float*)d_in[3];
    const float* qkvb  = (const float*)d_in[4];
    const float* projw = (const float*)d_in[5];
    const float* projb = (const float*)d_in[6];
    const float* rpb   = (const float*)d_in[7];
    const float* ln2w  = (const float*)d_in[8];
    const float* ln2b  = (const float*)d_in[9];
    const float* fc1w  = (const float*)d_in[10];
    const float* fc1b  = (const float*)d_in[11];
    const float* fc2w  = (const float*)d_in[12];
    const float* fc2b  = (const float*)d_in[13];
    const int*   ridx  = (const int*)  d_in[14];
    float* out = (float*)d_out;

    cudaFuncSetAttribute(attn_kernel, cudaFuncAttributeMaxDynamicSharedMemorySize,
                         SM_ATTN_FLOATS * (int)sizeof(float));
    cudaFuncSetAttribute(mlp_kernel, cudaFuncAttributeMaxDynamicSharedMemorySize,
                         SM_MLP_FLOATS * (int)sizeof(float));

    attn_kernel<<<NWIN, 256, SM_ATTN_FLOATS * sizeof(float)>>>(
        x, ln1w, ln1b, qkvw, qkvb, projw, projb, rpb, ln2w, ln2b, ridx);

    mlp_kernel<<<TTOK / 64, 256, SM_MLP_FLOATS * sizeof(float)>>>(
        fc1w, fc1b, fc2w, fc2b, out);
}